// round 2
// baseline (speedup 1.0000x reference)
#include <cuda_runtime.h>
#include <cstdint>

// NetVladCNN: B=64, D=512, H=W=32 (N=1024), K=64
// x: (B,D,H,W) fp32   w: (K,D)   c: (K,D)   out: (D,K,B) fp32
//
// Stage 1: features[b,k,n] = sum_d w[k,d] * x[b,d,n]      (GEMM, per b)
// Stage 2: a = softmax over h (n = h*32 + w_idx, softmax over n/32 groups)
//          NOTE: sum_n a[b,k,n] == 32 exactly (softmax sums to 1 per w column)
// Stage 3: V[b,k,d] = sum_n a[b,k,n]*x[b,d,n] - 32*c[k,d]  (GEMM, per b)
//          normalize over k (twice, with eps clamp), write out[d,k,b]

#define BB 64
#define DD 512
#define NN 1024
#define KK 64
#define EPSN 1e-12f

// scratch: features, then softmaxed a, layout [b][k][n]
__device__ float g_a[(size_t)BB * KK * NN];

// ---------- packed f32x2 helpers (full-rate fp32 FMA on sm_103a) ----------
__device__ __forceinline__ unsigned long long pack2(float lo, float hi) {
    unsigned long long r;
    asm("mov.b64 %0, {%1,%2};" : "=l"(r) : "f"(lo), "f"(hi));
    return r;
}
__device__ __forceinline__ void ffma2(unsigned long long& d,
                                      unsigned long long a,
                                      unsigned long long b) {
    asm("fma.rn.f32x2 %0, %1, %2, %0;" : "+l"(d) : "l"(a), "l"(b));
}
__device__ __forceinline__ float2 unpack2(unsigned long long v) {
    float2 f;
    asm("mov.b64 {%0,%1}, %2;" : "=f"(f.x), "=f"(f.y) : "l"(v));
    return f;
}

// ============================================================================
// Kernel 1: features GEMM. CTA tile: 64 k x 64 n, per b. 256 threads, 4x4/thread.
// ============================================================================
__global__ __launch_bounds__(256) void k_features(const float* __restrict__ x,
                                                  const float* __restrict__ wt) {
    __shared__ float sW[16][68];  // [dd][k], padded
    __shared__ float sX[16][64];  // [dd][n]

    const int b  = blockIdx.y;
    const int n0 = blockIdx.x * 64;
    const int t  = threadIdx.x;
    const int tx = t & 15;   // n dim (4 n each)
    const int ty = t >> 4;   // k dim (4 k each)

    const float* xb = x + (size_t)b * DD * NN;

    unsigned long long acc[4][2];
#pragma unroll
    for (int i = 0; i < 4; i++) { acc[i][0] = 0ull; acc[i][1] = 0ull; }

    const int lk = t >> 2;          // 0..63  (w-tile load row)
    const int lj = (t & 3) * 4;     // 0,4,8,12
    const int ld = t >> 4;          // 0..15  (x-tile load row)
    const int ln = (t & 15) * 4;    // n offset

    for (int d0 = 0; d0 < DD; d0 += 16) {
        // load w tile 64k x 16d, store transposed [d][k]
        {
            float4 v = *(const float4*)(wt + lk * DD + d0 + lj);
            sW[lj + 0][lk] = v.x; sW[lj + 1][lk] = v.y;
            sW[lj + 2][lk] = v.z; sW[lj + 3][lk] = v.w;
        }
        // load x tile 16d x 64n
        {
            float4 v = *(const float4*)(xb + (size_t)(d0 + ld) * NN + n0 + ln);
            *(float4*)&sX[ld][ln] = v;
        }
        __syncthreads();
#pragma unroll
        for (int dd = 0; dd < 16; dd++) {
            float4 wf = *(const float4*)&sW[dd][ty * 4];
            float4 xf = *(const float4*)&sX[dd][tx * 4];
            unsigned long long xp0 = pack2(xf.x, xf.y);
            unsigned long long xp1 = pack2(xf.z, xf.w);
            unsigned long long w0 = pack2(wf.x, wf.x);
            unsigned long long w1 = pack2(wf.y, wf.y);
            unsigned long long w2 = pack2(wf.z, wf.z);
            unsigned long long w3 = pack2(wf.w, wf.w);
            ffma2(acc[0][0], w0, xp0); ffma2(acc[0][1], w0, xp1);
            ffma2(acc[1][0], w1, xp0); ffma2(acc[1][1], w1, xp1);
            ffma2(acc[2][0], w2, xp0); ffma2(acc[2][1], w2, xp1);
            ffma2(acc[3][0], w3, xp0); ffma2(acc[3][1], w3, xp1);
        }
        __syncthreads();
    }

#pragma unroll
    for (int i = 0; i < 4; i++) {
        float2 p0 = unpack2(acc[i][0]);
        float2 p1 = unpack2(acc[i][1]);
        float4 v = make_float4(p0.x, p0.y, p1.x, p1.y);
        *(float4*)&g_a[((size_t)b * KK + ty * 4 + i) * NN + n0 + tx * 4] = v;
    }
}

// ============================================================================
// Kernel 2: softmax over h.  One block per (b,k) row of 1024 = 32 h x 32 w.
// thread t covers n = t + 256u  (h = t>>5 + 8u, w = t&31 fixed)
// ============================================================================
__global__ __launch_bounds__(256) void k_softmax() {
    __shared__ float red[8][33];
    const size_t base = (size_t)blockIdx.x * NN;
    const int t = threadIdx.x;
    const int q = t >> 5, w = t & 31;

    float v[4];
#pragma unroll
    for (int u = 0; u < 4; u++) v[u] = g_a[base + t + 256 * u];

    float m = fmaxf(fmaxf(v[0], v[1]), fmaxf(v[2], v[3]));
    red[q][w] = m;
    __syncthreads();
    float mm = red[0][w];
#pragma unroll
    for (int qq = 1; qq < 8; qq++) mm = fmaxf(mm, red[qq][w]);
    __syncthreads();

    float s = 0.f;
#pragma unroll
    for (int u = 0; u < 4; u++) { v[u] = __expf(v[u] - mm); s += v[u]; }
    red[q][w] = s;
    __syncthreads();
    float ss = red[0][w];
#pragma unroll
    for (int qq = 1; qq < 8; qq++) ss += red[qq][w];

    float inv = 1.0f / ss;
#pragma unroll
    for (int u = 0; u < 4; u++) g_a[base + t + 256 * u] = v[u] * inv;
}

// ============================================================================
// Kernel 3: V GEMM + normalize + transposed write.
// CTA tile: 64 k (full K) x 64 d, per b. 256 threads, 4x4/thread.
// V[k,d] = sum_n a[k,n]*x[d,n] - 32*c[k,d]; out[d,k,b] = V / (n1*n2)
// ============================================================================
__global__ __launch_bounds__(256) void k_vlad(const float* __restrict__ x,
                                              const float* __restrict__ c,
                                              float* __restrict__ out) {
    __shared__ float sA[16][68];   // [n][k]
    __shared__ float sX[16][68];   // [n][d]
    __shared__ float red[16][64];
    __shared__ float sinv[64];

    const int b  = blockIdx.y;
    const int d0 = blockIdx.x * 64;
    const int t  = threadIdx.x;
    const int tx = t & 15;   // d dim (4 d each)
    const int ty = t >> 4;   // k dim (4 k each)

    const float* xb = x + (size_t)b * DD * NN;
    const float* ab = g_a + (size_t)b * KK * NN;

    unsigned long long acc[4][2];
#pragma unroll
    for (int i = 0; i < 4; i++) { acc[i][0] = 0ull; acc[i][1] = 0ull; }

    const int lr = t >> 2;          // 0..63  (row: k for A, d for X)
    const int lj = (t & 3) * 4;     // 0,4,8,12 (n offset)

    for (int n0 = 0; n0 < NN; n0 += 16) {
        {
            float4 v = *(const float4*)(ab + (size_t)lr * NN + n0 + lj);
            sA[lj + 0][lr] = v.x; sA[lj + 1][lr] = v.y;
            sA[lj + 2][lr] = v.z; sA[lj + 3][lr] = v.w;
        }
        {
            float4 v = *(const float4*)(xb + (size_t)(d0 + lr) * NN + n0 + lj);
            sX[lj + 0][lr] = v.x; sX[lj + 1][lr] = v.y;
            sX[lj + 2][lr] = v.z; sX[lj + 3][lr] = v.w;
        }
        __syncthreads();
#pragma unroll
        for (int nn = 0; nn < 16; nn++) {
            float4 af = *(const float4*)&sA[nn][ty * 4];
            float4 xf = *(const float4*)&sX[nn][tx * 4];
            unsigned long long xp0 = pack2(xf.x, xf.y);
            unsigned long long xp1 = pack2(xf.z, xf.w);
            unsigned long long a0 = pack2(af.x, af.x);
            unsigned long long a1 = pack2(af.y, af.y);
            unsigned long long a2 = pack2(af.z, af.z);
            unsigned long long a3 = pack2(af.w, af.w);
            ffma2(acc[0][0], a0, xp0); ffma2(acc[0][1], a0, xp1);
            ffma2(acc[1][0], a1, xp0); ffma2(acc[1][1], a1, xp1);
            ffma2(acc[2][0], a2, xp0); ffma2(acc[2][1], a2, xp1);
            ffma2(acc[3][0], a3, xp0); ffma2(acc[3][1], a3, xp1);
        }
        __syncthreads();
    }

    // epilogue: V = acc - 32*c ; reduce sum(V^2) over k per d column
    float v[4][4];
    float p[4] = {0.f, 0.f, 0.f, 0.f};
#pragma unroll
    for (int i = 0; i < 4; i++) {
        float4 cf = *(const float4*)&c[(ty * 4 + i) * DD + d0 + tx * 4];
        float2 p0 = unpack2(acc[i][0]);
        float2 p1 = unpack2(acc[i][1]);
        v[i][0] = p0.x - 32.f * cf.x;
        v[i][1] = p0.y - 32.f * cf.y;
        v[i][2] = p1.x - 32.f * cf.z;
        v[i][3] = p1.y - 32.f * cf.w;
#pragma unroll
        for (int j = 0; j < 4; j++) p[j] += v[i][j] * v[i][j];
    }
#pragma unroll
    for (int j = 0; j < 4; j++) red[ty][tx * 4 + j] = p[j];
    __syncthreads();

    if (t < 64) {
        float s = 0.f;
#pragma unroll
        for (int q = 0; q < 16; q++) s += red[q][t];
        float n1 = fmaxf(sqrtf(s), EPSN);
        float n2 = fmaxf(sqrtf(s) / n1, EPSN);
        sinv[t] = 1.0f / (n1 * n2);
    }
    __syncthreads();

#pragma unroll
    for (int i = 0; i < 4; i++) {
#pragma unroll
        for (int j = 0; j < 4; j++) {
            int dg = d0 + tx * 4 + j;
            int kg = ty * 4 + i;
            out[((size_t)dg * KK + kg) * BB + b] = v[i][j] * sinv[tx * 4 + j];
        }
    }
}

// ============================================================================
extern "C" void kernel_launch(void* const* d_in, const int* in_sizes, int n_in,
                              void* d_out, int out_size) {
    const float* x  = (const float*)d_in[0];  // (B,D,H,W)
    const float* wt = (const float*)d_in[1];  // (K,D)
    const float* c  = (const float*)d_in[2];  // (K,D)
    float* out = (float*)d_out;               // (D,K,B)

    dim3 g1(NN / 64, BB);
    k_features<<<g1, 256>>>(x, wt);

    k_softmax<<<BB * KK, 256>>>();

    dim3 g2(DD / 64, BB);
    k_vlad<<<g2, 256>>>(x, c, out);
}